// round 7
// baseline (speedup 1.0000x reference)
#include <cuda_runtime.h>
#include <math.h>
#include <stdint.h>

#define SEQ   4096
#define INDIM 64
#define D     1024
#define G     4096      // 4*D
#define NCTA  148
#define RTHR  256

typedef unsigned long long u64;

// ---------------- scratch (device globals: allocation-free) ----------------
__device__ float g_x [(size_t)SEQ * D];        // 16 MB
__device__ float g_xg[(size_t)SEQ * G];        // 64 MB
__device__ float g_h1[(size_t)SEQ * D];        // 16 MB
// per-unit packets: [slot][unit] = {h, epoch_bits}; 8B stores are atomic
__device__ float2 g_pkt[2][D];

// ---------------- packed f32x2 helpers (Blackwell) ----------------
#define FMA2(d,a,b,c)  asm("fma.rn.f32x2 %0,%1,%2,%3;" : "=l"(d) : "l"(a), "l"(b), "l"(c))
#define PACK2(d,x)     asm("mov.b64 %0,{%1,%1};"       : "=l"(d) : "f"(x))
#define UNPACK2(lo,hi,v) asm("mov.b64 {%0,%1},%2;"     : "=f"(lo), "=f"(hi) : "l"(v))

__device__ __forceinline__ float sigmoid_fast(float x) {
    return 1.f / (1.f + __expf(-x));
}
__device__ __forceinline__ float tanh_fast(float x) {
    return 2.f / (1.f + __expf(-2.f * x)) - 1.f;
}

// 16B volatile load (sees both 8B packets atomically per half)
__device__ __forceinline__ float4 ll_load(const float4* p) {
    float4 v;
    asm volatile("ld.volatile.global.v4.f32 {%0,%1,%2,%3}, [%4];"
                 : "=f"(v.x), "=f"(v.y), "=f"(v.z), "=f"(v.w) : "l"(p) : "memory");
    return v;
}
// 8B volatile store {h, epoch} — single-sector atomic
__device__ __forceinline__ void ll_store8(float2* p, float h, unsigned e) {
    asm volatile("st.volatile.global.v2.f32 [%0], {%1,%2};"
                 :: "l"(p), "f"(h), "f"(__uint_as_float(e)) : "memory");
}

// ---------------- init: zero packets (epoch=0 == initial h=0) ----------------
__global__ void init_state_kernel() {
    int tid = threadIdx.x;
    for (int i = tid; i < 2 * D; i += blockDim.x)
        ((float2*)g_pkt)[i] = make_float2(0.f, 0.f);
}

// ---------------- SGEMM: C = A@B^T + bias1(+bias2), opt leaky; f32x2 inner ----------------
template<bool RELU>
__global__ __launch_bounds__(256) void sgemm_nt(
    const float* __restrict__ A, const float* __restrict__ B,
    float* __restrict__ C,
    const float* __restrict__ bias1, const float* __restrict__ bias2,
    int M, int N, int K)
{
    __shared__ __align__(16) float As[8][132];
    __shared__ __align__(16) float Bs[8][132];

    const int tid = threadIdx.x;
    const int bm = blockIdx.y, bn = blockIdx.x;
    const int ty = tid >> 4, tx = tid & 15;
    const int lrow = tid >> 1;
    const int lcol = (tid & 1) * 4;

    const float* Aptr = A + (size_t)(bm * 128 + lrow) * K + lcol;
    const float* Bptr = B + (size_t)(bn * 128 + lrow) * K + lcol;

    u64 acc2[8][4];
    #pragma unroll
    for (int i = 0; i < 8; i++)
        #pragma unroll
        for (int j = 0; j < 4; j++) acc2[i][j] = 0ull;

    for (int k0 = 0; k0 < K; k0 += 8) {
        float4 a = *(const float4*)(Aptr + k0);
        float4 b = *(const float4*)(Bptr + k0);
        __syncthreads();
        As[lcol + 0][lrow] = a.x; As[lcol + 1][lrow] = a.y;
        As[lcol + 2][lrow] = a.z; As[lcol + 3][lrow] = a.w;
        Bs[lcol + 0][lrow] = b.x; Bs[lcol + 1][lrow] = b.y;
        Bs[lcol + 2][lrow] = b.z; Bs[lcol + 3][lrow] = b.w;
        __syncthreads();
        #pragma unroll
        for (int k = 0; k < 8; k++) {
            float4 a0 = *(const float4*)&As[k][ty * 8];
            float4 a1 = *(const float4*)&As[k][ty * 8 + 4];
            const ulonglong2* bp = (const ulonglong2*)&Bs[k][tx * 8];
            ulonglong2 q0 = bp[0], q1 = bp[1];
            u64 bv[4] = {q0.x, q0.y, q1.x, q1.y};
            float av[8] = {a0.x,a0.y,a0.z,a0.w,a1.x,a1.y,a1.z,a1.w};
            u64 aa[8];
            #pragma unroll
            for (int i = 0; i < 8; i++) PACK2(aa[i], av[i]);
            #pragma unroll
            for (int i = 0; i < 8; i++)
                #pragma unroll
                for (int j = 0; j < 4; j++)
                    FMA2(acc2[i][j], aa[i], bv[j], acc2[i][j]);
        }
    }

    const int colbase = bn * 128 + tx * 8;
    float bb[8];
    #pragma unroll
    for (int j = 0; j < 8; j++) {
        float v = bias1 ? bias1[colbase + j] : 0.f;
        if (bias2) v += bias2[colbase + j];
        bb[j] = v;
    }
    #pragma unroll
    for (int i = 0; i < 8; i++) {
        int row = bm * 128 + ty * 8 + i;
        float* Crow = C + (size_t)row * N + colbase;
        float o[8];
        #pragma unroll
        for (int j = 0; j < 4; j++) UNPACK2(o[2*j], o[2*j+1], acc2[i][j]);
        #pragma unroll
        for (int j = 0; j < 8; j++) {
            float v = o[j] + bb[j];
            if (RELU) v = v > 0.f ? v : 0.01f * v;
            o[j] = v;
        }
        *(float4*)(Crow)     = make_float4(o[0], o[1], o[2], o[3]);
        *(float4*)(Crow + 4) = make_float4(o[4], o[5], o[6], o[7]);
    }
}

// ---------------- persistent LSTM recurrence: unit-per-warp, 1 barrier/step ----------------
// 148 CTAs x 256 thr (8 warps), 1 CTA/SM.
//   all 256 threads: poll 4 units each (two 16B volatile loads of per-unit
//                    {h,epoch} packets, backoff) -> STS.128 into hs[parity].
//   warp 7        : also prefetches xg(t+1) into registers, stages xgs[parity].
//   ONE __syncthreads.
//   warps 0..nu-1 : warp w owns ALL 4 gate rows of unit u_begin+w in registers
//                   (128 regs). matvec -> 4 butterfly reduces -> lanes 0-3
//                   gate nonlinearities -> lane 0: c update (register), h,
//                   PUBLISH {h, t+1} immediately, then history stores.
// Two-slot parity safety: publish(t+1) requires this CTA's bar(t), which
// requires all packets at epoch t, which requires every CTA's bar(t-1) --
// so every thread chip-wide has finished polling epoch t-1 before its slot
// is overwritten.
__global__ __launch_bounds__(RTHR, 1) void lstm_recur_kernel(
    const float* __restrict__ Whh,   // [G][D] this layer
    const float* __restrict__ xg,    // [SEQ][G]
    float* __restrict__ h_hist,
    float* __restrict__ out,
    int store_hist, int store_out)
{
    __shared__ __align__(16) float4 hs4[2][D / 4];   // h assembled, parity buffered
    __shared__ float xgs[2][4][8];                   // [parity][gate][unit]

    const int tid  = threadIdx.x;
    const int lane = tid & 31;
    const int wid  = tid >> 5;
    const int cta  = blockIdx.x;

    const int u_begin = (cta * D) / NCTA;
    const int u_end   = ((cta + 1) * D) / NCTA;
    const int nu      = u_end - u_begin;       // 6 or 7

    // ---- poller: thread tid polls units 4*tid .. 4*tid+3 ----
    const float4* pk0 = (const float4*)&g_pkt[0][0] + 2 * tid;   // 2 float4 = 4 units
    const float4* pk1 = (const float4*)&g_pkt[1][0] + 2 * tid;

    // ---- warp 7: xg prefetch (4*nu values) ----
    const bool ldr = (wid == 7) && (lane < 4 * nu);
    int my_grow = 0, xg_g = 0, xg_u = 0; float xr = 0.f;
    if (ldr) {
        xg_g = lane / nu; xg_u = lane - xg_g * nu;
        my_grow = xg_g * D + u_begin + xg_u;
        xr = __ldg(&xg[my_grow]);              // prefetch t=0
    }

    // ---- matvec warps: warp w owns unit u = u_begin + w, all 4 gate rows ----
    const bool act = (wid < nu);
    const int u = u_begin + wid;
    ulonglong2 wv[4][8];                       // 4 gates x 8 x 16B = 128 regs
    if (act) {
        #pragma unroll
        for (int gidx = 0; gidx < 4; gidx++) {
            const ulonglong2* W = (const ulonglong2*)(Whh + (size_t)(gidx * D + u) * D);
            #pragma unroll
            for (int j = 0; j < 8; j++)
                wv[gidx][j] = W[j * 32 + lane];
        }
    }
    float c_reg = 0.f;
    float2* pub0 = &g_pkt[0][u < D ? u : 0];
    float2* pub1 = &g_pkt[1][u < D ? u : 0];
    __syncthreads();

    for (int t = 0; t < SEQ; t++) {
        // ---- phase 1: poll 4 units (backoff), STS.128 into hs[parity] ----
        {
            const float4* pA = (t & 1) ? pk1 : pk0;
            const unsigned want = (unsigned)t;
            float4 A = ll_load(pA);
            float4 B = ll_load(pA + 1);
            while (__float_as_uint(A.y) != want || __float_as_uint(A.w) != want ||
                   __float_as_uint(B.y) != want || __float_as_uint(B.w) != want) {
                __nanosleep(60);
                A = ll_load(pA);
                B = ll_load(pA + 1);
            }
            hs4[t & 1][tid] = make_float4(A.x, A.z, B.x, B.z);
        }
        if (ldr) {
            xgs[t & 1][xg_g][xg_u] = xr;
            if (t + 1 < SEQ) xr = __ldg(&xg[(size_t)(t + 1) * G + my_grow]);
        }
        __syncthreads();   // the only barrier per step

        // ---- phase 2: matvec + reduce + gates + publish (each unit-warp) ----
        if (act) {
            const ulonglong2* hp = (const ulonglong2*)hs4[t & 1];
            u64 ax[4], ay[4];
            #pragma unroll
            for (int gidx = 0; gidx < 4; gidx++) { ax[gidx] = 0ull; ay[gidx] = 0ull; }
            #pragma unroll
            for (int j = 0; j < 8; j++) {
                ulonglong2 hv = hp[j * 32 + lane];
                #pragma unroll
                for (int gidx = 0; gidx < 4; gidx++) {
                    FMA2(ax[gidx], wv[gidx][j].x, hv.x, ax[gidx]);
                    FMA2(ay[gidx], wv[gidx][j].y, hv.y, ay[gidx]);
                }
            }
            float s[4];
            #pragma unroll
            for (int gidx = 0; gidx < 4; gidx++) {
                float xl, xh, yl, yh;
                UNPACK2(xl, xh, ax[gidx]); UNPACK2(yl, yh, ay[gidx]);
                s[gidx] = (xl + xh) + (yl + yh);
            }
            #pragma unroll
            for (int off = 16; off; off >>= 1) {
                s[0] += __shfl_xor_sync(0xffffffffu, s[0], off);
                s[1] += __shfl_xor_sync(0xffffffffu, s[1], off);
                s[2] += __shfl_xor_sync(0xffffffffu, s[2], off);
                s[3] += __shfl_xor_sync(0xffffffffu, s[3], off);
            }
            // lanes 0-3: gate nonlinearities in parallel
            float pre = (lane == 0) ? s[0] : (lane == 1) ? s[1]
                      : (lane == 2) ? s[2] : s[3];
            pre += xgs[t & 1][lane & 3][wid];
            float nl = (lane == 2) ? tanh_fast(pre) : sigmoid_fast(pre);
            float gi = __shfl_sync(0xffffffffu, nl, 0);
            float gf = __shfl_sync(0xffffffffu, nl, 1);
            float gg = __shfl_sync(0xffffffffu, nl, 2);
            float go = __shfl_sync(0xffffffffu, nl, 3);
            if (lane == 0) {
                c_reg = gf * c_reg + gi * gg;
                float h = go * tanh_fast(c_reg);
                if (t + 1 < SEQ)
                    ll_store8(((t + 1) & 1) ? pub1 : pub0, h, (unsigned)(t + 1));
                if (store_hist) h_hist[(size_t)t * D + u] = h;
                if (store_out && t == SEQ - 1)
                    out[u] = h > 0.f ? h : 0.01f * h;
            }
        }
    }
}

// ---------------- launch ----------------
extern "C" void kernel_launch(void* const* d_in, const int* in_sizes, int n_in,
                              void* d_out, int out_size)
{
    const float* inp = (const float*)d_in[0];   // (4096, 64)
    const float* W1  = (const float*)d_in[1];   // (1024, 64)
    const float* b1  = (const float*)d_in[2];   // (1024,)
    const float* Wih = (const float*)d_in[3];   // (2, 4096, 1024)
    const float* Whh = (const float*)d_in[4];   // (2, 4096, 1024)
    const float* bih = (const float*)d_in[5];   // (2, 4096)
    const float* bhh = (const float*)d_in[6];   // (2, 4096)
    float* out = (float*)d_out;                 // (1,1,1024)

    float *gx, *gxg, *gh1;
    cudaGetSymbolAddress((void**)&gx,  g_x);
    cudaGetSymbolAddress((void**)&gxg, g_xg);
    cudaGetSymbolAddress((void**)&gh1, g_h1);

    // Phase A: x = leaky_relu(inp @ W1^T + b1)
    sgemm_nt<true><<<dim3(D / 128, SEQ / 128), 256>>>(
        inp, W1, gx, b1, nullptr, SEQ, D, INDIM);

    // Phase B: xg1 = x @ Wih1^T + (bih1 + bhh1)
    sgemm_nt<false><<<dim3(G / 128, SEQ / 128), 256>>>(
        gx, Wih, gxg, bih, bhh, SEQ, G, D);

    // Layer-1 recurrence (writes g_h1)
    init_state_kernel<<<1, 1024>>>();
    lstm_recur_kernel<<<NCTA, RTHR>>>(Whh, gxg, gh1, out, 1, 0);

    // Phase C: xg2 = h1 @ Wih2^T + (bih2 + bhh2)
    sgemm_nt<false><<<dim3(G / 128, SEQ / 128), 256>>>(
        gh1, Wih + (size_t)G * D, gxg, bih + G, bhh + G, SEQ, G, D);

    // Layer-2 recurrence (writes final leaky_relu(h_T) to out)
    init_state_kernel<<<1, 1024>>>();
    lstm_recur_kernel<<<NCTA, RTHR>>>(Whh + (size_t)G * D, gxg, gh1, out, 0, 1);
}

// round 8
// speedup vs baseline: 1.4841x; 1.4841x over previous
#include <cuda_runtime.h>
#include <math.h>
#include <stdint.h>

#define SEQ   4096
#define INDIM 64
#define D     1024
#define G     4096      // 4*D
#define NCTA  148
#define RTHR  512
#define NCHUNK (NCTA * 3)   // 444 LL packets (3 per CTA, some partial/inactive)

typedef unsigned long long u64;

// ---------------- scratch (device globals: allocation-free) ----------------
__device__ float g_x [(size_t)SEQ * D];        // 16 MB
__device__ float g_xg[(size_t)SEQ * G];        // 64 MB
__device__ float g_h1[(size_t)SEQ * D];        // 16 MB
// LL packets: [slot][cta][chunk] = {h0,h1,h2, epoch_bits}
__device__ float4 g_ll[2][NCTA][3];

// ---------------- packed f32x2 helpers (Blackwell) ----------------
#define FMA2(d,a,b,c)  asm("fma.rn.f32x2 %0,%1,%2,%3;" : "=l"(d) : "l"(a), "l"(b), "l"(c))
#define PACK2(d,x)     asm("mov.b64 %0,{%1,%1};"       : "=l"(d) : "f"(x))
#define UNPACK2(lo,hi,v) asm("mov.b64 {%0,%1},%2;"     : "=f"(lo), "=f"(hi) : "l"(v))

__device__ __forceinline__ float sigmoid_fast(float x) {
    return 1.f / (1.f + __expf(-x));
}
__device__ __forceinline__ float tanh_fast(float x) {
    return 2.f / (1.f + __expf(-2.f * x)) - 1.f;
}

// 16B volatile (L2-coherent, single-sector-atomic) load/store — NCCL LL style.
__device__ __forceinline__ float4 ll_load(const float4* p) {
    float4 v;
    asm volatile("ld.volatile.global.v4.f32 {%0,%1,%2,%3}, [%4];"
                 : "=f"(v.x), "=f"(v.y), "=f"(v.z), "=f"(v.w) : "l"(p) : "memory");
    return v;
}
__device__ __forceinline__ void ll_store(float4* p, float4 v) {
    asm volatile("st.volatile.global.v4.f32 [%0], {%1,%2,%3,%4};"
                 :: "l"(p), "f"(v.x), "f"(v.y), "f"(v.z), "f"(v.w) : "memory");
}

// ---------------- init: zero LL packets (epoch=0, h=0) ----------------
__global__ void init_state_kernel() {
    int tid = threadIdx.x;
    float4 z = make_float4(0.f, 0.f, 0.f, 0.f);
    for (int i = tid; i < 2 * NCTA * 3; i += blockDim.x)
        ((float4*)g_ll)[i] = z;
}

// ---------------- SGEMM: C = A@B^T + bias1(+bias2), opt leaky; f32x2 inner ----------------
template<bool RELU>
__global__ __launch_bounds__(256) void sgemm_nt(
    const float* __restrict__ A, const float* __restrict__ B,
    float* __restrict__ C,
    const float* __restrict__ bias1, const float* __restrict__ bias2,
    int M, int N, int K)
{
    __shared__ __align__(16) float As[8][132];
    __shared__ __align__(16) float Bs[8][132];

    const int tid = threadIdx.x;
    const int bm = blockIdx.y, bn = blockIdx.x;
    const int ty = tid >> 4, tx = tid & 15;
    const int lrow = tid >> 1;
    const int lcol = (tid & 1) * 4;

    const float* Aptr = A + (size_t)(bm * 128 + lrow) * K + lcol;
    const float* Bptr = B + (size_t)(bn * 128 + lrow) * K + lcol;

    u64 acc2[8][4];
    #pragma unroll
    for (int i = 0; i < 8; i++)
        #pragma unroll
        for (int j = 0; j < 4; j++) acc2[i][j] = 0ull;

    for (int k0 = 0; k0 < K; k0 += 8) {
        float4 a = *(const float4*)(Aptr + k0);
        float4 b = *(const float4*)(Bptr + k0);
        __syncthreads();
        As[lcol + 0][lrow] = a.x; As[lcol + 1][lrow] = a.y;
        As[lcol + 2][lrow] = a.z; As[lcol + 3][lrow] = a.w;
        Bs[lcol + 0][lrow] = b.x; Bs[lcol + 1][lrow] = b.y;
        Bs[lcol + 2][lrow] = b.z; Bs[lcol + 3][lrow] = b.w;
        __syncthreads();
        #pragma unroll
        for (int k = 0; k < 8; k++) {
            float4 a0 = *(const float4*)&As[k][ty * 8];
            float4 a1 = *(const float4*)&As[k][ty * 8 + 4];
            const ulonglong2* bp = (const ulonglong2*)&Bs[k][tx * 8];
            ulonglong2 q0 = bp[0], q1 = bp[1];
            u64 bv[4] = {q0.x, q0.y, q1.x, q1.y};
            float av[8] = {a0.x,a0.y,a0.z,a0.w,a1.x,a1.y,a1.z,a1.w};
            u64 aa[8];
            #pragma unroll
            for (int i = 0; i < 8; i++) PACK2(aa[i], av[i]);
            #pragma unroll
            for (int i = 0; i < 8; i++)
                #pragma unroll
                for (int j = 0; j < 4; j++)
                    FMA2(acc2[i][j], aa[i], bv[j], acc2[i][j]);
        }
    }

    const int colbase = bn * 128 + tx * 8;
    float bb[8];
    #pragma unroll
    for (int j = 0; j < 8; j++) {
        float v = bias1 ? bias1[colbase + j] : 0.f;
        if (bias2) v += bias2[colbase + j];
        bb[j] = v;
    }
    #pragma unroll
    for (int i = 0; i < 8; i++) {
        int row = bm * 128 + ty * 8 + i;
        float* Crow = C + (size_t)row * N + colbase;
        float o[8];
        #pragma unroll
        for (int j = 0; j < 4; j++) UNPACK2(o[2*j], o[2*j+1], acc2[i][j]);
        #pragma unroll
        for (int j = 0; j < 8; j++) {
            float v = o[j] + bb[j];
            if (RELU) v = v > 0.f ? v : 0.01f * v;
            o[j] = v;
        }
        *(float4*)(Crow)     = make_float4(o[0], o[1], o[2], o[3]);
        *(float4*)(Crow + 4) = make_float4(o[4], o[5], o[6], o[7]);
    }
}

// ---------------- persistent LSTM recurrence: LL + backoff poll + 1 barrier ----------------
// R6 resource shape (512 thr, 444 pollers, 2 rows/warp) with the barrier count
// cut from 3 to 1:
//   warps 0-13 : poll LL packet (backoff) -> hs[par]; ONE bar.sync(1,480);
//                reg matvec, shfl reduce, STS gs, fence, done[wid]=t+1.
//   warp 14    : xgs[par] stage + done[14]=t+1, then next xg prefetch; bar.
//   warp 15    : NO barriers. Spins on done[], gates, PUBLISHES first, then
//                history stores.
// Epoch-chain safety: gs(t+1)/hs((t+1)&1)/xgs((t+1)&1) writes all happen after
// bar1(t+1) <- own CTA's poll(t+1) <- own publish(t+1) <- warp15 finished
// reading gs(t)/xgs(t&1). hs,xgs parity double-buffered; gs single (chain above).
__global__ __launch_bounds__(RTHR, 1) void lstm_recur_kernel(
    const float* __restrict__ Whh,   // [G][D] this layer
    const float* __restrict__ xg,    // [SEQ][G]
    float* __restrict__ h_hist,
    float* __restrict__ out,
    int store_hist, int store_out)
{
    __shared__ __align__(16) float hs[2][D];
    __shared__ float gs[32];
    __shared__ float xgs[2][32];
    __shared__ volatile unsigned done[16];

    const int tid  = threadIdx.x;
    const int lane = tid & 31;
    const int wid  = tid >> 5;
    const int cta  = blockIdx.x;

    const int u_begin = (cta * D) / NCTA;
    const int u_end   = ((cta + 1) * D) / NCTA;
    const int nu      = u_end - u_begin;       // 6 or 7
    const int nrows   = 4 * nu;                // 24 or 28

    // ---- poller mapping (tid < 444): chunk tid = (cta c, sub k) ----
    const bool pact = (tid < NCHUNK);
    int p_ub = 0, p_n = 0;
    const float4* p_src0 = nullptr;
    const float4* p_src1 = nullptr;
    if (pact) {
        int c = tid / 3, k = tid - c * 3;
        int cb = (c * D) / NCTA, ce = ((c + 1) * D) / NCTA;
        p_ub = cb + 3 * k;
        p_n  = ce - p_ub; p_n = p_n > 3 ? 3 : p_n;   // may be <=0 -> inactive
        p_src0 = &g_ll[0][c][k];
        p_src1 = &g_ll[1][c][k];
    }
    const bool p_on = pact && (p_n > 0);

    // ---- warp 14: xg prefetch ----
    const bool ldr = (wid == 14) && (lane < nrows);
    int my_grow = 0; float xr = 0.f;
    if (ldr) {
        int gate = lane / nu, ui = lane - gate * nu;
        my_grow = gate * D + u_begin + ui;
        xr = __ldg(&xg[my_grow]);              // prefetch t=0
    }

    // ---- matvec warps 0-13: rows r0=2w, r1=2w+1, weights in registers ----
    const int r0 = wid * 2, r1 = r0 + 1;
    const bool act = (wid < 14) && (r0 < nrows);
    ulonglong2 wr0[8], wr1[8];
    if (act) {
        int gg0 = r0 / nu, gg1 = r1 / nu;
        int grow0 = gg0 * D + u_begin + (r0 - gg0 * nu);
        int grow1 = gg1 * D + u_begin + (r1 - gg1 * nu);
        const ulonglong2* W0 = (const ulonglong2*)(Whh + (size_t)grow0 * D);
        const ulonglong2* W1 = (const ulonglong2*)(Whh + (size_t)grow1 * D);
        #pragma unroll
        for (int j = 0; j < 8; j++) {
            wr0[j] = W0[j * 32 + lane];
            wr1[j] = W1[j * 32 + lane];
        }
    }

    // ---- warp 15: gate lane roles ----
    const bool gw = (wid == 15);
    const bool g_on = lane < nrows;
    const int  g_of = g_on ? lane / nu : 0;
    const bool u_on = lane < nu;
    float c_reg = 0.f;
    float4* pub0 = &g_ll[0][cta][lane < 3 ? lane : 0];
    float4* pub1 = &g_ll[1][cta][lane < 3 ? lane : 0];
    const bool pub_on = (lane < 3) && (3 * lane < nu);
    // which done[] slots warp15 must wait on
    const bool req = (lane < 14 && 2 * lane < nrows) || (lane == 14);

    if (tid < 16) done[tid] = 0u;
    __syncthreads();   // the only full-CTA barrier

    for (int t = 0; t < SEQ; t++) {
        if (wid < 15) {
            // ---- phase 1: ingest h(t) (backoff poll) / stage xg(t) ----
            if (p_on) {
                const float4* src = (t & 1) ? p_src1 : p_src0;
                const unsigned want = (unsigned)t;
                float4 v = ll_load(src);             // first try: free if ready
                while (__float_as_uint(v.w) != want) {
                    __nanosleep(50);
                    v = ll_load(src);
                }
                float* hsd = hs[t & 1];
                hsd[p_ub] = v.x;
                if (p_n > 1) hsd[p_ub + 1] = v.y;
                if (p_n > 2) hsd[p_ub + 2] = v.z;
            }
            if (wid == 14) {
                if (ldr) xgs[t & 1][lane] = xr;
                __syncwarp();
                if (lane == 0) { __threadfence_block(); done[14] = (unsigned)(t + 1); }
                if (ldr && t + 1 < SEQ) xr = __ldg(&xg[(size_t)(t + 1) * G + my_grow]);
            }
            asm volatile("bar.sync 1, 480;" ::: "memory");

            // ---- phase 2: matvec + warp reduce + signal warp15 ----
            if (act) {
                const ulonglong2* hp = (const ulonglong2*)hs[t & 1];
                u64 a0 = 0ull, a1 = 0ull, b0 = 0ull, b1 = 0ull;
                #pragma unroll
                for (int j = 0; j < 8; j++) {
                    ulonglong2 hv = hp[j * 32 + lane];
                    FMA2(a0, wr0[j].x, hv.x, a0);
                    FMA2(a1, wr0[j].y, hv.y, a1);
                    FMA2(b0, wr1[j].x, hv.x, b0);
                    FMA2(b1, wr1[j].y, hv.y, b1);
                }
                float a0l, a0h, a1l, a1h, b0l, b0h, b1l, b1h;
                UNPACK2(a0l, a0h, a0); UNPACK2(a1l, a1h, a1);
                UNPACK2(b0l, b0h, b0); UNPACK2(b1l, b1h, b1);
                float acc0 = (a0l + a0h) + (a1l + a1h);
                float acc1 = (b0l + b0h) + (b1l + b1h);
                #pragma unroll
                for (int off = 16; off; off >>= 1) {
                    acc0 += __shfl_xor_sync(0xffffffffu, acc0, off);
                    acc1 += __shfl_xor_sync(0xffffffffu, acc1, off);
                }
                if (lane == 0) {
                    gs[r0] = acc0; gs[r1] = acc1;
                    __threadfence_block();
                    done[wid] = (unsigned)(t + 1);
                }
            }
        } else {
            // ---- warp 15: wait for gate inputs (smem spin, no barrier) ----
            const unsigned tgt = (unsigned)(t + 1);
            for (;;) {
                bool ok = !req || (done[lane] >= tgt);
                if (__all_sync(0xffffffffu, ok)) break;
            }
            __threadfence_block();   // acquire gs/xgs

            float nl = 0.f;
            if (g_on) {
                float val = gs[lane] + xgs[t & 1][lane];
                nl = (g_of == 2) ? tanh_fast(val) : sigmoid_fast(val);
            }
            float gi = __shfl_sync(0xffffffffu, nl, 0 * nu + lane);
            float gf = __shfl_sync(0xffffffffu, nl, 1 * nu + lane);
            float gg = __shfl_sync(0xffffffffu, nl, 2 * nu + lane);
            float go = __shfl_sync(0xffffffffu, nl, 3 * nu + lane);
            float h = 0.f;
            if (u_on) {
                c_reg = gf * c_reg + gi * gg;
                h = go * tanh_fast(c_reg);
            }
            // pack chunks and PUBLISH FIRST (inter-CTA critical path)
            float h0 = __shfl_sync(0xffffffffu, h, 3 * lane + 0);
            float h1 = __shfl_sync(0xffffffffu, h, 3 * lane + 1);
            float h2 = __shfl_sync(0xffffffffu, h, 3 * lane + 2);
            if (pub_on && t + 1 < SEQ) {
                float4 pkt = make_float4(h0, h1, h2, __uint_as_float((unsigned)(t + 1)));
                ll_store(((t + 1) & 1) ? pub1 : pub0, pkt);
            }
            if (u_on) {
                if (store_hist) h_hist[(size_t)t * D + u_begin + lane] = h;
                if (store_out && t == SEQ - 1)
                    out[u_begin + lane] = h > 0.f ? h : 0.01f * h;
            }
        }
    }
}

// ---------------- launch ----------------
extern "C" void kernel_launch(void* const* d_in, const int* in_sizes, int n_in,
                              void* d_out, int out_size)
{
    const float* inp = (const float*)d_in[0];   // (4096, 64)
    const float* W1  = (const float*)d_in[1];   // (1024, 64)
    const float* b1  = (const float*)d_in[2];   // (1024,)
    const float* Wih = (const float*)d_in[3];   // (2, 4096, 1024)
    const float* Whh = (const float*)d_in[4];   // (2, 4096, 1024)
    const float* bih = (const float*)d_in[5];   // (2, 4096)
    const float* bhh = (const float*)d_in[6];   // (2, 4096)
    float* out = (float*)d_out;                 // (1,1,1024)

    float *gx, *gxg, *gh1;
    cudaGetSymbolAddress((void**)&gx,  g_x);
    cudaGetSymbolAddress((void**)&gxg, g_xg);
    cudaGetSymbolAddress((void**)&gh1, g_h1);

    // Phase A: x = leaky_relu(inp @ W1^T + b1)
    sgemm_nt<true><<<dim3(D / 128, SEQ / 128), 256>>>(
        inp, W1, gx, b1, nullptr, SEQ, D, INDIM);

    // Phase B: xg1 = x @ Wih1^T + (bih1 + bhh1)
    sgemm_nt<false><<<dim3(G / 128, SEQ / 128), 256>>>(
        gx, Wih, gxg, bih, bhh, SEQ, G, D);

    // Layer-1 recurrence (writes g_h1)
    init_state_kernel<<<1, 1024>>>();
    lstm_recur_kernel<<<NCTA, RTHR>>>(Whh, gxg, gh1, out, 1, 0);

    // Phase C: xg2 = h1 @ Wih2^T + (bih2 + bhh2)
    sgemm_nt<false><<<dim3(G / 128, SEQ / 128), 256>>>(
        gh1, Wih + (size_t)G * D, gxg, bih + G, bhh + G, SEQ, G, D);

    // Layer-2 recurrence (writes final leaky_relu(h_T) to out)
    init_state_kernel<<<1, 1024>>>();
    lstm_recur_kernel<<<NCTA, RTHR>>>(Whh + (size_t)G * D, gxg, gh1, out, 0, 1);
}

// round 9
// speedup vs baseline: 1.5742x; 1.0608x over previous
#include <cuda_runtime.h>
#include <math.h>
#include <stdint.h>

#define SEQ   4096
#define INDIM 64
#define D     1024
#define G     4096      // 4*D
#define NCTA  148
#define RTHR  512
#define NCHUNK (NCTA * 3)   // 444 LL packets (3 per CTA, some partial/inactive)

typedef unsigned long long u64;

// ---------------- scratch (device globals: allocation-free) ----------------
__device__ float g_x [(size_t)SEQ * D];        // 16 MB
__device__ float g_xg[(size_t)SEQ * G];        // 64 MB
__device__ float g_h1[(size_t)SEQ * D];        // 16 MB
// LL packets: [slot][cta][chunk] = {h0,h1,h2, epoch_bits}
__device__ float4 g_ll[2][NCTA][3];

// ---------------- packed f32x2 helpers (Blackwell) ----------------
#define FMA2(d,a,b,c)  asm("fma.rn.f32x2 %0,%1,%2,%3;" : "=l"(d) : "l"(a), "l"(b), "l"(c))
#define PACK2(d,x)     asm("mov.b64 %0,{%1,%1};"       : "=l"(d) : "f"(x))
#define UNPACK2(lo,hi,v) asm("mov.b64 {%0,%1},%2;"     : "=f"(lo), "=f"(hi) : "l"(v))

__device__ __forceinline__ float sigmoid_fast(float x) {
    return 1.f / (1.f + __expf(-x));
}
__device__ __forceinline__ float tanh_fast(float x) {
    return 2.f / (1.f + __expf(-2.f * x)) - 1.f;
}

// 16B volatile (L2-coherent, single-sector-atomic) load/store — NCCL LL style.
__device__ __forceinline__ float4 ll_load(const float4* p) {
    float4 v;
    asm volatile("ld.volatile.global.v4.f32 {%0,%1,%2,%3}, [%4];"
                 : "=f"(v.x), "=f"(v.y), "=f"(v.z), "=f"(v.w) : "l"(p) : "memory");
    return v;
}
__device__ __forceinline__ void ll_store(float4* p, float4 v) {
    asm volatile("st.volatile.global.v4.f32 [%0], {%1,%2,%3,%4};"
                 :: "l"(p), "f"(v.x), "f"(v.y), "f"(v.z), "f"(v.w) : "memory");
}

// ---------------- init: zero LL packets (epoch=0 == state S_0 = 0) ----------------
__global__ void init_state_kernel() {
    int tid = threadIdx.x;
    float4 z = make_float4(0.f, 0.f, 0.f, 0.f);
    for (int i = tid; i < 2 * NCTA * 3; i += blockDim.x)
        ((float4*)g_ll)[i] = z;
}

// ---------------- SGEMM: C = A@B^T + bias1(+bias2), opt leaky; f32x2 inner ----------------
template<bool RELU>
__global__ __launch_bounds__(256) void sgemm_nt(
    const float* __restrict__ A, const float* __restrict__ B,
    float* __restrict__ C,
    const float* __restrict__ bias1, const float* __restrict__ bias2,
    int M, int N, int K)
{
    __shared__ __align__(16) float As[8][132];
    __shared__ __align__(16) float Bs[8][132];

    const int tid = threadIdx.x;
    const int bm = blockIdx.y, bn = blockIdx.x;
    const int ty = tid >> 4, tx = tid & 15;
    const int lrow = tid >> 1;
    const int lcol = (tid & 1) * 4;

    const float* Aptr = A + (size_t)(bm * 128 + lrow) * K + lcol;
    const float* Bptr = B + (size_t)(bn * 128 + lrow) * K + lcol;

    u64 acc2[8][4];
    #pragma unroll
    for (int i = 0; i < 8; i++)
        #pragma unroll
        for (int j = 0; j < 4; j++) acc2[i][j] = 0ull;

    for (int k0 = 0; k0 < K; k0 += 8) {
        float4 a = *(const float4*)(Aptr + k0);
        float4 b = *(const float4*)(Bptr + k0);
        __syncthreads();
        As[lcol + 0][lrow] = a.x; As[lcol + 1][lrow] = a.y;
        As[lcol + 2][lrow] = a.z; As[lcol + 3][lrow] = a.w;
        Bs[lcol + 0][lrow] = b.x; Bs[lcol + 1][lrow] = b.y;
        Bs[lcol + 2][lrow] = b.z; Bs[lcol + 3][lrow] = b.w;
        __syncthreads();
        #pragma unroll
        for (int k = 0; k < 8; k++) {
            float4 a0 = *(const float4*)&As[k][ty * 8];
            float4 a1 = *(const float4*)&As[k][ty * 8 + 4];
            const ulonglong2* bp = (const ulonglong2*)&Bs[k][tx * 8];
            ulonglong2 q0 = bp[0], q1 = bp[1];
            u64 bv[4] = {q0.x, q0.y, q1.x, q1.y};
            float av[8] = {a0.x,a0.y,a0.z,a0.w,a1.x,a1.y,a1.z,a1.w};
            u64 aa[8];
            #pragma unroll
            for (int i = 0; i < 8; i++) PACK2(aa[i], av[i]);
            #pragma unroll
            for (int i = 0; i < 8; i++)
                #pragma unroll
                for (int j = 0; j < 4; j++)
                    FMA2(acc2[i][j], aa[i], bv[j], acc2[i][j]);
        }
    }

    const int colbase = bn * 128 + tx * 8;
    float bb[8];
    #pragma unroll
    for (int j = 0; j < 8; j++) {
        float v = bias1 ? bias1[colbase + j] : 0.f;
        if (bias2) v += bias2[colbase + j];
        bb[j] = v;
    }
    #pragma unroll
    for (int i = 0; i < 8; i++) {
        int row = bm * 128 + ty * 8 + i;
        float* Crow = C + (size_t)row * N + colbase;
        float o[8];
        #pragma unroll
        for (int j = 0; j < 4; j++) UNPACK2(o[2*j], o[2*j+1], acc2[i][j]);
        #pragma unroll
        for (int j = 0; j < 8; j++) {
            float v = o[j] + bb[j];
            if (RELU) v = v > 0.f ? v : 0.01f * v;
            o[j] = v;
        }
        *(float4*)(Crow)     = make_float4(o[0], o[1], o[2], o[3]);
        *(float4*)(Crow + 4) = make_float4(o[4], o[5], o[6], o[7]);
    }
}

// ---------------- persistent LSTM recurrence: LL + pipelined gates, 2 barriers ----------------
// 148 CTAs x 512 thr (R6 resource shape). State S_e lives in LL packets with
// epoch e; S_0 = 0 from init.
// Per loop iteration t (t = 0..SEQ-1), TWO plain __syncthreads:
//   phase A: warps 0-13 poll S_t (backoff) -> hs;  warp 14 stages xg[t] into
//            xgs[t&1] and prefetches xg[t+1];  warp 15 (t>0): computes gates
//            for step t-1 from gs (=Whh@S_{t-1}) + xgs[(t-1)&1], PUBLISHES
//            S_t (epoch t) — concurrently with everyone polling for it — then
//            stores h_hist[t-1].
//   bar;  phase B: warps 0-13 matvec hs -> gs;  bar.
// Epilogue: warp 15 computes step SEQ-1, writes h_hist[SEQ-1] / out.
// Safety: gs written in phase B(t), read by warp15 in phase A(t+1) — separated
// by bar2(t); next write in phase B(t+1) after bar1(t+1) which warp15 joins.
// hs written phase A(t), read phase B(t), rewritten phase A(t+1) after bar2(t).
// xgs parity-buffered (w14 writes t while w15 reads t-1). Packet slot parity:
// publish(t) <- own bar2(t-1) <- own poll(t-1) <- all publish(t-1) <- all
// bar2(t-2) <- all pollers done with epoch t-2: overwrite of slot t&1 is safe.
__global__ __launch_bounds__(RTHR, 1) void lstm_recur_kernel(
    const float* __restrict__ Whh,   // [G][D] this layer
    const float* __restrict__ xg,    // [SEQ][G]
    float* __restrict__ h_hist,
    float* __restrict__ out,
    int store_hist, int store_out)
{
    __shared__ __align__(16) float hs[D];
    __shared__ float gs[32];
    __shared__ float xgs[2][32];

    const int tid  = threadIdx.x;
    const int lane = tid & 31;
    const int wid  = tid >> 5;
    const int cta  = blockIdx.x;

    const int u_begin = (cta * D) / NCTA;
    const int u_end   = ((cta + 1) * D) / NCTA;
    const int nu      = u_end - u_begin;       // 6 or 7
    const int nrows   = 4 * nu;                // 24 or 28

    // ---- poller mapping (tid < 444, i.e. warps 0-13): chunk = (cta c, sub k) ----
    const bool pact = (tid < NCHUNK);
    int p_ub = 0, p_n = 0;
    const float4* p_src0 = nullptr;
    const float4* p_src1 = nullptr;
    if (pact) {
        int c = tid / 3, k = tid - c * 3;
        int cb = (c * D) / NCTA, ce = ((c + 1) * D) / NCTA;
        p_ub = cb + 3 * k;
        p_n  = ce - p_ub; p_n = p_n > 3 ? 3 : p_n;   // may be <=0 -> inactive
        p_src0 = &g_ll[0][c][k];
        p_src1 = &g_ll[1][c][k];
    }
    const bool p_on = pact && (p_n > 0);

    // ---- warp 14: xg prefetch ----
    const bool ldr = (wid == 14) && (lane < nrows);
    int my_grow = 0; float xr = 0.f;
    if (ldr) {
        int gate = lane / nu, ui = lane - gate * nu;
        my_grow = gate * D + u_begin + ui;
        xr = __ldg(&xg[my_grow]);              // prefetch t=0
    }

    // ---- matvec warps 0-13: rows r0=2w, r1=2w+1, weights in registers ----
    const int r0 = wid * 2, r1 = r0 + 1;
    const bool act = (wid < 14) && (r0 < nrows);
    ulonglong2 wr0[8], wr1[8];
    if (act) {
        int gg0 = r0 / nu, gg1 = r1 / nu;
        int grow0 = gg0 * D + u_begin + (r0 - gg0 * nu);
        int grow1 = gg1 * D + u_begin + (r1 - gg1 * nu);
        const ulonglong2* W0 = (const ulonglong2*)(Whh + (size_t)grow0 * D);
        const ulonglong2* W1 = (const ulonglong2*)(Whh + (size_t)grow1 * D);
        #pragma unroll
        for (int j = 0; j < 8; j++) {
            wr0[j] = W0[j * 32 + lane];
            wr1[j] = W1[j * 32 + lane];
        }
    }

    // ---- warp 15: gate lane roles ----
    const bool gw = (wid == 15);
    const bool g_on = lane < nrows;
    const int  g_of = g_on ? lane / nu : 0;
    const bool u_on = lane < nu;
    float c_reg = 0.f;
    float4* pub0 = &g_ll[0][cta][lane < 3 ? lane : 0];
    float4* pub1 = &g_ll[1][cta][lane < 3 ? lane : 0];
    const bool pub_on = (lane < 3) && (3 * lane < nu);

    __syncthreads();

    for (int t = 0; t < SEQ; t++) {
        // ================= phase A =================
        if (wid < 14) {
            if (p_on) {
                const float4* src = (t & 1) ? p_src1 : p_src0;
                const unsigned want = (unsigned)t;
                float4 v = ll_load(src);             // first try: free if ready
                while (__float_as_uint(v.w) != want) {
                    __nanosleep(40);
                    v = ll_load(src);
                }
                hs[p_ub] = v.x;
                if (p_n > 1) hs[p_ub + 1] = v.y;
                if (p_n > 2) hs[p_ub + 2] = v.z;
            }
        } else if (wid == 14) {
            if (ldr) {
                xgs[t & 1][lane] = xr;
                if (t + 1 < SEQ) xr = __ldg(&xg[(size_t)(t + 1) * G + my_grow]);
            }
        } else if (t > 0) {
            // warp 15: finish step t-1 (gs = Whh@S_{t-1}), publish S_t
            float nl = 0.f;
            if (g_on) {
                float val = gs[lane] + xgs[(t - 1) & 1][lane];
                nl = (g_of == 2) ? tanh_fast(val) : sigmoid_fast(val);
            }
            float gi = __shfl_sync(0xffffffffu, nl, 0 * nu + lane);
            float gf = __shfl_sync(0xffffffffu, nl, 1 * nu + lane);
            float gg = __shfl_sync(0xffffffffu, nl, 2 * nu + lane);
            float go = __shfl_sync(0xffffffffu, nl, 3 * nu + lane);
            float h = 0.f;
            if (u_on) {
                c_reg = gf * c_reg + gi * gg;
                h = go * tanh_fast(c_reg);
            }
            float h0 = __shfl_sync(0xffffffffu, h, 3 * lane + 0);
            float h1 = __shfl_sync(0xffffffffu, h, 3 * lane + 1);
            float h2 = __shfl_sync(0xffffffffu, h, 3 * lane + 2);
            if (pub_on) {
                float4 pkt = make_float4(h0, h1, h2, __uint_as_float((unsigned)t));
                ll_store((t & 1) ? pub1 : pub0, pkt);
            }
            if (u_on && store_hist)
                h_hist[(size_t)(t - 1) * D + u_begin + lane] = h;
        }
        __syncthreads();   // bar1: hs/xgs ready; warp15 done with gs(t-1)

        // ================= phase B =================
        if (act) {
            const ulonglong2* hp = (const ulonglong2*)hs;
            u64 a0 = 0ull, a1 = 0ull, b0 = 0ull, b1 = 0ull;
            #pragma unroll
            for (int j = 0; j < 8; j++) {
                ulonglong2 hv = hp[j * 32 + lane];
                FMA2(a0, wr0[j].x, hv.x, a0);
                FMA2(a1, wr0[j].y, hv.y, a1);
                FMA2(b0, wr1[j].x, hv.x, b0);
                FMA2(b1, wr1[j].y, hv.y, b1);
            }
            float a0l, a0h, a1l, a1h, b0l, b0h, b1l, b1h;
            UNPACK2(a0l, a0h, a0); UNPACK2(a1l, a1h, a1);
            UNPACK2(b0l, b0h, b0); UNPACK2(b1l, b1h, b1);
            float acc0 = (a0l + a0h) + (a1l + a1h);
            float acc1 = (b0l + b0h) + (b1l + b1h);
            #pragma unroll
            for (int off = 16; off; off >>= 1) {
                acc0 += __shfl_xor_sync(0xffffffffu, acc0, off);
                acc1 += __shfl_xor_sync(0xffffffffu, acc1, off);
            }
            if (lane == 0) { gs[r0] = acc0; gs[r1] = acc1; }
        }
        __syncthreads();   // bar2: gs(t) ready for warp15's next phase A
    }

    // ---- epilogue: step SEQ-1 gates (no publish needed) ----
    if (gw) {
        float nl = 0.f;
        if (g_on) {
            float val = gs[lane] + xgs[(SEQ - 1) & 1][lane];
            nl = (g_of == 2) ? tanh_fast(val) : sigmoid_fast(val);
        }
        float gi = __shfl_sync(0xffffffffu, nl, 0 * nu + lane);
        float gf = __shfl_sync(0xffffffffu, nl, 1 * nu + lane);
        float gg = __shfl_sync(0xffffffffu, nl, 2 * nu + lane);
        float go = __shfl_sync(0xffffffffu, nl, 3 * nu + lane);
        if (u_on) {
            c_reg = gf * c_reg + gi * gg;
            float h = go * tanh_fast(c_reg);
            if (store_hist) h_hist[(size_t)(SEQ - 1) * D + u_begin + lane] = h;
            if (store_out) out[u_begin + lane] = h > 0.f ? h : 0.01f * h;
        }
    }
}

// ---------------- launch ----------------
extern "C" void kernel_launch(void* const* d_in, const int* in_sizes, int n_in,
                              void* d_out, int out_size)
{
    const float* inp = (const float*)d_in[0];   // (4096, 64)
    const float* W1  = (const float*)d_in[1];   // (1024, 64)
    const float* b1  = (const float*)d_in[2];   // (1024,)
    const float* Wih = (const float*)d_in[3];   // (2, 4096, 1024)
    const float* Whh = (const float*)d_in[4];   // (2, 4096, 1024)
    const float* bih = (const float*)d_in[5];   // (2, 4096)
    const float* bhh = (const float*)d_in[6];   // (2, 4096)
    float* out = (float*)d_out;                 // (1,1,1024)

    float *gx, *gxg, *gh1;
    cudaGetSymbolAddress((void**)&gx,  g_x);
    cudaGetSymbolAddress((void**)&gxg, g_xg);
    cudaGetSymbolAddress((void**)&gh1, g_h1);

    // Phase A: x = leaky_relu(inp @ W1^T + b1)
    sgemm_nt<true><<<dim3(D / 128, SEQ / 128), 256>>>(
        inp, W1, gx, b1, nullptr, SEQ, D, INDIM);

    // Phase B: xg1 = x @ Wih1^T + (bih1 + bhh1)
    sgemm_nt<false><<<dim3(G / 128, SEQ / 128), 256>>>(
        gx, Wih, gxg, bih, bhh, SEQ, G, D);

    // Layer-1 recurrence (writes g_h1)
    init_state_kernel<<<1, 1024>>>();
    lstm_recur_kernel<<<NCTA, RTHR>>>(Whh, gxg, gh1, out, 1, 0);

    // Phase C: xg2 = h1 @ Wih2^T + (bih2 + bhh2)
    sgemm_nt<false><<<dim3(G / 128, SEQ / 128), 256>>>(
        gh1, Wih + (size_t)G * D, gxg, bih + G, bhh + G, SEQ, G, D);

    // Layer-2 recurrence (writes final leaky_relu(h_T) to out)
    init_state_kernel<<<1, 1024>>>();
    lstm_recur_kernel<<<NCTA, RTHR>>>(Whh + (size_t)G * D, gxg, gh1, out, 0, 1);
}

// round 10
// speedup vs baseline: 2.0686x; 1.3141x over previous
#include <cuda_runtime.h>
#include <math.h>
#include <stdint.h>

#define SEQ   4096
#define INDIM 64
#define D     1024
#define G     4096      // 4*D
#define NCTA  148
#define RTHR  512
#define NCHUNK (NCTA * 3)   // 444 LL packets (3 per CTA, some partial/inactive)

typedef unsigned long long u64;

// ---------------- scratch (device globals: allocation-free) ----------------
__device__ float g_x [(size_t)SEQ * D];        // 16 MB
__device__ float g_xg[(size_t)SEQ * G];        // 64 MB
__device__ float g_h1[(size_t)SEQ * D];        // 16 MB
// LL packets: [slot][cta][chunk] = {h0,h1,h2, epoch_bits}
__device__ float4 g_ll[2][NCTA][3];

// ---------------- packed f32x2 helpers (Blackwell) ----------------
#define FMA2(d,a,b,c)  asm("fma.rn.f32x2 %0,%1,%2,%3;" : "=l"(d) : "l"(a), "l"(b), "l"(c))
#define PACK2(d,x)     asm("mov.b64 %0,{%1,%1};"       : "=l"(d) : "f"(x))
#define UNPACK2(lo,hi,v) asm("mov.b64 {%0,%1},%2;"     : "=f"(lo), "=f"(hi) : "l"(v))

__device__ __forceinline__ float sigmoid_fast(float x) {
    return 1.f / (1.f + __expf(-x));
}
__device__ __forceinline__ float tanh_fast(float x) {
    return 2.f / (1.f + __expf(-2.f * x)) - 1.f;
}

// 16B volatile (L2-coherent, single-sector-atomic) load/store — NCCL LL style.
__device__ __forceinline__ float4 ll_load(const float4* p) {
    float4 v;
    asm volatile("ld.volatile.global.v4.f32 {%0,%1,%2,%3}, [%4];"
                 : "=f"(v.x), "=f"(v.y), "=f"(v.z), "=f"(v.w) : "l"(p) : "memory");
    return v;
}
__device__ __forceinline__ void ll_store(float4* p, float4 v) {
    asm volatile("st.volatile.global.v4.f32 [%0], {%1,%2,%3,%4};"
                 :: "l"(p), "f"(v.x), "f"(v.y), "f"(v.z), "f"(v.w) : "memory");
}

// ---------------- init: zero LL packets (epoch=0, h=0) ----------------
__global__ void init_state_kernel() {
    int tid = threadIdx.x;
    float4 z = make_float4(0.f, 0.f, 0.f, 0.f);
    for (int i = tid; i < 2 * NCTA * 3; i += blockDim.x)
        ((float4*)g_ll)[i] = z;
}

// ---------------- SGEMM: C = A@B^T + bias1(+bias2), opt leaky; f32x2 inner ----------------
template<bool RELU>
__global__ __launch_bounds__(256) void sgemm_nt(
    const float* __restrict__ A, const float* __restrict__ B,
    float* __restrict__ C,
    const float* __restrict__ bias1, const float* __restrict__ bias2,
    int M, int N, int K)
{
    __shared__ __align__(16) float As[8][132];
    __shared__ __align__(16) float Bs[8][132];

    const int tid = threadIdx.x;
    const int bm = blockIdx.y, bn = blockIdx.x;
    const int ty = tid >> 4, tx = tid & 15;
    const int lrow = tid >> 1;
    const int lcol = (tid & 1) * 4;

    const float* Aptr = A + (size_t)(bm * 128 + lrow) * K + lcol;
    const float* Bptr = B + (size_t)(bn * 128 + lrow) * K + lcol;

    u64 acc2[8][4];
    #pragma unroll
    for (int i = 0; i < 8; i++)
        #pragma unroll
        for (int j = 0; j < 4; j++) acc2[i][j] = 0ull;

    for (int k0 = 0; k0 < K; k0 += 8) {
        float4 a = *(const float4*)(Aptr + k0);
        float4 b = *(const float4*)(Bptr + k0);
        __syncthreads();
        As[lcol + 0][lrow] = a.x; As[lcol + 1][lrow] = a.y;
        As[lcol + 2][lrow] = a.z; As[lcol + 3][lrow] = a.w;
        Bs[lcol + 0][lrow] = b.x; Bs[lcol + 1][lrow] = b.y;
        Bs[lcol + 2][lrow] = b.z; Bs[lcol + 3][lrow] = b.w;
        __syncthreads();
        #pragma unroll
        for (int k = 0; k < 8; k++) {
            float4 a0 = *(const float4*)&As[k][ty * 8];
            float4 a1 = *(const float4*)&As[k][ty * 8 + 4];
            const ulonglong2* bp = (const ulonglong2*)&Bs[k][tx * 8];
            ulonglong2 q0 = bp[0], q1 = bp[1];
            u64 bv[4] = {q0.x, q0.y, q1.x, q1.y};
            float av[8] = {a0.x,a0.y,a0.z,a0.w,a1.x,a1.y,a1.z,a1.w};
            u64 aa[8];
            #pragma unroll
            for (int i = 0; i < 8; i++) PACK2(aa[i], av[i]);
            #pragma unroll
            for (int i = 0; i < 8; i++)
                #pragma unroll
                for (int j = 0; j < 4; j++)
                    FMA2(acc2[i][j], aa[i], bv[j], acc2[i][j]);
        }
    }

    const int colbase = bn * 128 + tx * 8;
    float bb[8];
    #pragma unroll
    for (int j = 0; j < 8; j++) {
        float v = bias1 ? bias1[colbase + j] : 0.f;
        if (bias2) v += bias2[colbase + j];
        bb[j] = v;
    }
    #pragma unroll
    for (int i = 0; i < 8; i++) {
        int row = bm * 128 + ty * 8 + i;
        float* Crow = C + (size_t)row * N + colbase;
        float o[8];
        #pragma unroll
        for (int j = 0; j < 4; j++) UNPACK2(o[2*j], o[2*j+1], acc2[i][j]);
        #pragma unroll
        for (int j = 0; j < 8; j++) {
            float v = o[j] + bb[j];
            if (RELU) v = v > 0.f ? v : 0.01f * v;
            o[j] = v;
        }
        *(float4*)(Crow)     = make_float4(o[0], o[1], o[2], o[3]);
        *(float4*)(Crow + 4) = make_float4(o[4], o[5], o[6], o[7]);
    }
}

// ---------------- persistent LSTM recurrence (R6 structure, reshaped poll) ----------------
// 148 CTAs x 512 thr, 3 __syncthreads/step (R6's proven shape).
// Changes vs R6:
//  (a) poll schedule: immediate first poll, then one nanosleep(180), then a
//      tight 60ns loop — halves mid-window poll bursts (L2 decongestion) while
//      keeping detect overshoot small.
//  (b) matvec lane 0 adds xg and applies the gate nonlinearity BEFORE storing
//      gs (parallel across 14 warps); warp 15 is just 4 LDS + c-update + tanh
//      + publish — its serial shfl-gather chain is gone.
__global__ __launch_bounds__(RTHR, 1) void lstm_recur_kernel(
    const float* __restrict__ Whh,   // [G][D] this layer
    const float* __restrict__ xg,    // [SEQ][G]
    float* __restrict__ h_hist,
    float* __restrict__ out,
    int store_hist, int store_out)
{
    __shared__ __align__(16) float hs[D];   // assembled h(t)
    __shared__ float gs[32];                // nonlinearized gate values
    __shared__ float xgs[32];

    const int tid  = threadIdx.x;
    const int lane = tid & 31;
    const int wid  = tid >> 5;
    const int cta  = blockIdx.x;

    const int u_begin = (cta * D) / NCTA;
    const int u_end   = ((cta + 1) * D) / NCTA;
    const int nu      = u_end - u_begin;       // 6 or 7
    const int nrows   = 4 * nu;                // 24 or 28

    // ---- poller mapping (tid < 444): chunk tid = (cta c, sub k) ----
    const bool pact = (tid < NCHUNK);
    int p_ub = 0, p_n = 0;
    const float4* p_src0 = nullptr;
    const float4* p_src1 = nullptr;
    if (pact) {
        int c = tid / 3, k = tid - c * 3;
        int cb = (c * D) / NCTA, ce = ((c + 1) * D) / NCTA;
        p_ub = cb + 3 * k;
        p_n  = ce - p_ub; p_n = p_n > 3 ? 3 : p_n;   // may be <=0 -> inactive
        p_src0 = &g_ll[0][c][k];
        p_src1 = &g_ll[1][c][k];
    }
    const bool p_on = pact && (p_n > 0);

    // ---- xg prefetch threads (warp 14, tids 448+) ----
    const bool ldr = (tid >= 448) && (tid - 448 < nrows);
    int my_grow = 0; float xr = 0.f;
    if (ldr) {
        int r = tid - 448;
        int gate = r / nu, ui = r - gate * nu;
        my_grow = gate * D + u_begin + ui;
        xr = __ldg(&xg[my_grow]);              // prefetch t=0
    }

    // ---- matvec warps 0-13: rows r0=2w, r1=2w+1, weights in registers ----
    const int r0 = wid * 2, r1 = r0 + 1;
    const bool act = (wid < 14) && (r0 < nrows);
    int gate0 = 0, gate1 = 0;                  // gate index of each row
    ulonglong2 wr0[8], wr1[8];
    if (act) {
        gate0 = r0 / nu; gate1 = r1 / nu;
        int grow0 = gate0 * D + u_begin + (r0 - gate0 * nu);
        int grow1 = gate1 * D + u_begin + (r1 - gate1 * nu);
        const ulonglong2* W0 = (const ulonglong2*)(Whh + (size_t)grow0 * D);
        const ulonglong2* W1 = (const ulonglong2*)(Whh + (size_t)grow1 * D);
        #pragma unroll
        for (int j = 0; j < 8; j++) {
            wr0[j] = W0[j * 32 + lane];
            wr1[j] = W1[j * 32 + lane];
        }
    }

    // ---- warp 15: per-unit combine + publish ----
    const bool gw = (wid == 15);
    const bool u_on = lane < nu;
    float c_reg = 0.f;
    float4* pub0 = nullptr; float4* pub1 = nullptr;
    bool pub_on = false;
    if (gw) {
        pub_on = (lane < 3) && (3 * lane < nu);
        if (lane < 3) { pub0 = &g_ll[0][cta][lane]; pub1 = &g_ll[1][cta][lane]; }
    }
    __syncthreads();

    for (int t = 0; t < SEQ; t++) {
        // ---- phase 1: ingest h(t) via LL packets (reshaped poll) / stage xg(t) ----
        if (p_on) {
            const float4* src = (t & 1) ? p_src1 : p_src0;
            const unsigned want = (unsigned)t;
            float4 v = ll_load(src);                 // immediate: free if ready
            if (__float_as_uint(v.w) != want) {
                __nanosleep(180);                    // skip the dead window
                v = ll_load(src);
                while (__float_as_uint(v.w) != want) {
                    __nanosleep(60);                 // tight tail
                    v = ll_load(src);
                }
            }
            hs[p_ub] = v.x;
            if (p_n > 1) hs[p_ub + 1] = v.y;
            if (p_n > 2) hs[p_ub + 2] = v.z;
        } else if (ldr) {
            xgs[tid - 448] = xr;
            if (t + 1 < SEQ) xr = __ldg(&xg[(size_t)(t + 1) * G + my_grow]);
        }
        __syncthreads();

        // ---- phase 2: matvec + warp reduce + nonlinearity at source ----
        if (act) {
            u64 a0 = 0ull, a1 = 0ull, b0 = 0ull, b1 = 0ull;
            #pragma unroll
            for (int j = 0; j < 8; j++) {
                ulonglong2 hv = ((const ulonglong2*)hs)[j * 32 + lane];
                FMA2(a0, wr0[j].x, hv.x, a0);
                FMA2(a1, wr0[j].y, hv.y, a1);
                FMA2(b0, wr1[j].x, hv.x, b0);
                FMA2(b1, wr1[j].y, hv.y, b1);
            }
            float a0l, a0h, a1l, a1h, b0l, b0h, b1l, b1h;
            UNPACK2(a0l, a0h, a0); UNPACK2(a1l, a1h, a1);
            UNPACK2(b0l, b0h, b0); UNPACK2(b1l, b1h, b1);
            float acc0 = (a0l + a0h) + (a1l + a1h);
            float acc1 = (b0l + b0h) + (b1l + b1h);
            #pragma unroll
            for (int off = 16; off; off >>= 1) {
                acc0 += __shfl_xor_sync(0xffffffffu, acc0, off);
                acc1 += __shfl_xor_sync(0xffffffffu, acc1, off);
            }
            if (lane == 0) {
                float v0 = acc0 + xgs[r0];
                float v1 = acc1 + xgs[r1];
                gs[r0] = (gate0 == 2) ? tanh_fast(v0) : sigmoid_fast(v0);
                gs[r1] = (gate1 == 2) ? tanh_fast(v1) : sigmoid_fast(v1);
            }
        }
        __syncthreads();

        // ---- phase 3: combine + publish-first (warp 15 only) ----
        if (gw) {
            float h = 0.f;
            if (u_on) {
                float gi = gs[0 * nu + lane];
                float gf = gs[1 * nu + lane];
                float gg = gs[2 * nu + lane];
                float go = gs[3 * nu + lane];
                c_reg = gf * c_reg + gi * gg;
                h = go * tanh_fast(c_reg);
            }
            float h0 = __shfl_sync(0xffffffffu, h, 3 * lane + 0);
            float h1 = __shfl_sync(0xffffffffu, h, 3 * lane + 1);
            float h2 = __shfl_sync(0xffffffffu, h, 3 * lane + 2);
            if (pub_on && t + 1 < SEQ) {
                float4 pkt = make_float4(h0, h1, h2, __uint_as_float((unsigned)(t + 1)));
                ll_store(((t + 1) & 1) ? pub1 : pub0, pkt);
            }
            if (u_on) {
                if (store_hist) h_hist[(size_t)t * D + u_begin + lane] = h;
                if (store_out && t == SEQ - 1)
                    out[u_begin + lane] = h > 0.f ? h : 0.01f * h;
            }
        }
        __syncthreads();   // protect hs/xgs/gs for next iteration
    }
}

// ---------------- launch ----------------
extern "C" void kernel_launch(void* const* d_in, const int* in_sizes, int n_in,
                              void* d_out, int out_size)
{
    const float* inp = (const float*)d_in[0];   // (4096, 64)
    const float* W1  = (const float*)d_in[1];   // (1024, 64)
    const float* b1  = (const float*)d_in[2];   // (1024,)
    const float* Wih = (const float*)d_in[3];   // (2, 4096, 1024)
    const float* Whh = (const float*)d_in[4];   // (2, 4096, 1024)
    const float* bih = (const float*)d_in[5];   // (2, 4096)
    const float* bhh = (const float*)d_in[6];   // (2, 4096)
    float* out = (float*)d_out;                 // (1,1,1024)

    float *gx, *gxg, *gh1;
    cudaGetSymbolAddress((void**)&gx,  g_x);
    cudaGetSymbolAddress((void**)&gxg, g_xg);
    cudaGetSymbolAddress((void**)&gh1, g_h1);

    // Phase A: x = leaky_relu(inp @ W1^T + b1)
    sgemm_nt<true><<<dim3(D / 128, SEQ / 128), 256>>>(
        inp, W1, gx, b1, nullptr, SEQ, D, INDIM);

    // Phase B: xg1 = x @ Wih1^T + (bih1 + bhh1)
    sgemm_nt<false><<<dim3(G / 128, SEQ / 128), 256>>>(
        gx, Wih, gxg, bih, bhh, SEQ, G, D);

    // Layer-1 recurrence (writes g_h1)
    init_state_kernel<<<1, 1024>>>();
    lstm_recur_kernel<<<NCTA, RTHR>>>(Whh, gxg, gh1, out, 1, 0);

    // Phase C: xg2 = h1 @ Wih2^T + (bih2 + bhh2)
    sgemm_nt<false><<<dim3(G / 128, SEQ / 128), 256>>>(
        gh1, Wih + (size_t)G * D, gxg, bih + G, bhh + G, SEQ, G, D);

    // Layer-2 recurrence (writes final leaky_relu(h_T) to out)
    init_state_kernel<<<1, 1024>>>();
    lstm_recur_kernel<<<NCTA, RTHR>>>(Whh + (size_t)G * D, gxg, gh1, out, 0, 1);
}